// round 13
// baseline (speedup 1.0000x reference)
#include <cuda_runtime.h>
#include <cstdint>

// ---------------------------------------------------------------------------
// CVQNN classifier: out[b,w] = log1p(relu(c0[w] + mx'^2 + mp'^2))
//   mx'[w] = sum_k A[k][w]   *x[b,k] + bias[w]     (A = S[rows,:64], bias=d/2)
//   mp'[w] = sum_k A[k][10+w]*x[b,k] + bias[10+w]
// Single launch, non-persistent grid, one 512-row tile per block. Block 0
// computes A/bias/c0 in-kernel, publishes via flag. 128 threads, 4 rows/thr
// (halves the A-broadcast LDS stream per row — L1 was the binding pipe).
// Pipeline: 8 chunks of 8 k-floats, 4-buffer ring; chunks 0-3 staged up
// front, chunk c+4 staged after COMPUTE(c) (thread-local WAR, ordered by
// program order). Warp-private slabs: per-warp cp.async waits + __syncwarp,
// zero block barriers in the hot path.
// ---------------------------------------------------------------------------

__device__ __align__(16) float g_A[64 * 20];   // A[k][o] = S[rows[o], k]
__device__ __align__(16) float g_bias[20];     // d[rows[o]] / 2
__device__ __align__(16) float g_c0[10];       // cov_term[w]/4 - 0.5
__device__ volatile int g_flag = 0;            // 0 until first publish

// ---------------- f32x2 packed-math helpers --------------------------------
#define FMA2(acc, a, b) \
    asm("fma.rn.f32x2 %0, %1, %2, %0;" : "+l"(acc) : "l"(a), "l"(b))
#define MUL2(d, a, b) \
    asm("mul.rn.f32x2 %0, %1, %2;" : "=l"(d) : "l"(a), "l"(b))
#define ADD2(d, a, b) \
    asm("add.rn.f32x2 %0, %1, %2;" : "=l"(d) : "l"(a), "l"(b))
#define PACK_DUP(d, f) \
    asm("mov.b64 %0, {%1, %1};" : "=l"(d) : "f"(f))
#define UNPACK2(lo, hi, v) \
    asm("mov.b64 {%0, %1}, %2;" : "=f"(lo), "=f"(hi) : "l"(v))

// ---------------------------------------------------------------------------
// Setup (block 0 only, 128 threads): row-backward propagation v^T <- v^T * F.
// ---------------------------------------------------------------------------

__device__ __forceinline__ void bs_back(float v[20], float* sv,
                                        const float* p, int start, int tid) {
    const int m = tid & 63;
    const bool lower = tid < 64;
    const bool active = (m >= start) && (m < start + ((start == 0) ? 64 : 62));
#pragma unroll
    for (int w = 0; w < 20; ++w) sv[w * 132 + tid] = v[w];
    __syncthreads();
    if (active) {
        const int rel = m - start;
        const int i = start + (rel & ~1);
        const bool is_i = (rel & 1) == 0;
        float st_, ct_, sp_, cp_;
        __sincosf(p[3 * i], &st_, &ct_);
        __sincosf(p[3 * i + 1], &sp_, &cp_);
        const int o = is_i ? (i + 1) : i;
        const int sameIdx = (lower ? 0 : 64) + o;
        const int crossIdx = (lower ? 64 : 0) + o;
        const float cA1 = (is_i ? cp_ : -cp_) * st_;
        const float cA2 = (lower ? sp_ : -sp_) * st_;
#pragma unroll
        for (int w = 0; w < 20; ++w)
            v[w] = ct_ * v[w] + cA1 * sv[w * 132 + sameIdx]
                              + cA2 * sv[w * 132 + crossIdx];
    }
    __syncthreads();
}

__device__ __forceinline__ void r_back(float v[20], float* sv,
                                       const float* p, int tid) {
    const int k = tid & 63;
    const bool lower = tid < 64;
    float c_ = 1.0f, s_ = 0.0f;
    if (k < 63) __sincosf(p[3 * k + 2], &s_, &c_);
#pragma unroll
    for (int w = 0; w < 20; ++w) sv[w * 132 + tid] = v[w];
    __syncthreads();
    const float cs = lower ? s_ : -s_;
    const int cross = tid ^ 64;
#pragma unroll
    for (int w = 0; w < 20; ++w)
        v[w] = c_ * v[w] + cs * sv[w * 132 + cross];
    __syncthreads();
}

__device__ void run_setup(float* sv,
                          const float* i1_0, const float* sq0,
                          const float* i2_0, const float* d0,
                          const float* i1_1, const float* sq1,
                          const float* i2_1, const float* d1, int tid) {
    const int k = tid & 63;
    const bool lower = tid < 64;
    float v[20];
#pragma unroll
    for (int w = 0; w < 20; ++w) {
        const int r = (w < 10) ? w : (54 + w);  // rows = [0..9, 64..73]
        v[w] = (tid == r) ? 1.0f : 0.0f;
    }
    // ---- layer 1 (leftmost in S) ----
    bs_back(v, sv, i2_1, 1, tid);
    bs_back(v, sv, i2_1, 0, tid);
    {
        const float e = lower ? __expf(-sq1[k]) : __expf(sq1[k]);
#pragma unroll
        for (int w = 0; w < 20; ++w) v[w] *= e;
    }
    r_back(v, sv, i1_1, tid);
    bs_back(v, sv, i1_1, 1, tid);
    bs_back(v, sv, i1_1, 0, tid);
    // dot0 = row_r(M_L1) . [2*disp0; 0]
#pragma unroll
    for (int w = 0; w < 20; ++w)
        sv[w * 132 + tid] = lower ? v[w] * 2.0f * d0[tid] : 0.0f;
    __syncthreads();
    if (tid < 20) {
        float s = 0.0f;
        for (int t = 0; t < 64; ++t) s += sv[tid * 132 + t];
        sv[2640 + tid] = s;
    }
    __syncthreads();
    // ---- layer 0 ----
    bs_back(v, sv, i2_0, 1, tid);
    bs_back(v, sv, i2_0, 0, tid);
    {
        const float e = lower ? __expf(-sq0[k]) : __expf(sq0[k]);
#pragma unroll
        for (int w = 0; w < 20; ++w) v[w] *= e;
    }
    r_back(v, sv, i1_0, tid);
    bs_back(v, sv, i1_0, 1, tid);
    bs_back(v, sv, i1_0, 0, tid);
    // ---- outputs ----
    if (lower) {
#pragma unroll
        for (int o = 0; o < 20; ++o) g_A[tid * 20 + o] = v[o];
    }
#pragma unroll
    for (int w = 0; w < 10; ++w)
        sv[w * 132 + tid] = v[w] * v[w] + v[w + 10] * v[w + 10];
    __syncthreads();
    if (tid < 10) {
        float s = 0.0f;
        for (int t = 0; t < 128; ++t) s += sv[tid * 132 + t];
        g_c0[tid] = 0.25f * s - 0.5f;
    }
    if (tid < 20) {
        float b = 0.5f * sv[2640 + tid];
        if (tid < 10) b += d1[tid];
        g_bias[tid] = b;
    }
    __syncthreads();
    __threadfence();
    if (tid == 0) g_flag = 1;
}

// ---------------------------------------------------------------------------
// Main: 128 threads, 4 rows/thread, 512-row tile, 8 chunks, 4-buffer ring.
// smem: A (1312 floats) + 4 buffers of 512 rows x 2 float4 (16 KB each).
// Swizzle: f4i = 2*row + (q ^ ((row>>2)&1))  -> conflict-free LDS.128.
// Warp w owns rows {e*128 + w*32 + lane, e=0..3}: per-warp sync only.
// ---------------------------------------------------------------------------

#define A_FLOATS   1312
#define CBUF       4096                     // floats per chunk buffer (16 KB)
#define SMEM_BYTES ((A_FLOATS + 4 * CBUF) * 4)

#define CP_COMMIT() asm volatile("cp.async.commit_group;" ::: "memory")
#define CP_WAIT(N)  asm volatile("cp.async.wait_group %0;" :: "n"(N) : "memory")

// stage this warp's 128 rows of chunk C (k-floats [8C,8C+8)) into buffer BUF
#define STAGEW(C, BUF)                                                        \
    do {                                                                      \
        _Pragma("unroll")                                                     \
        for (int it = 0; it < 8; ++it) {                                      \
            const int flat = (it << 5) + lane;   /* 0..255 */                 \
            const int sr = flat >> 1, qq = flat & 1;                          \
            const int rloc = ((sr >> 5) << 7) + (wid << 5) + (sr & 31);       \
            int grow = base + rloc;                                           \
            if (grow > Bm1) grow = Bm1;                                       \
            const int f4i = (rloc << 1) + (qq ^ ((rloc >> 2) & 1));           \
            const unsigned sa = sbase + (A_FLOATS * 4u) +                     \
                                (BUF) * (CBUF * 4u) + (unsigned)f4i * 16u;    \
            const float4* gp = x4 + (size_t)grow * 16 + (C) * 2 + qq;         \
            asm volatile("cp.async.cg.shared.global [%0], [%1], 16;"          \
                         :: "r"(sa), "l"(gp) : "memory");                     \
        }                                                                     \
        CP_COMMIT();                                                          \
    } while (0)

// consume chunk C from buffer BUF: 8 k x 4 rows x 10 FFMA2
#define COMPUTE(C, BUF)                                                       \
    do {                                                                      \
        const float4* s4 =                                                    \
            reinterpret_cast<const float4*>(sx + A_FLOATS + (BUF) * CBUF);    \
        float4 xv[4][2];                                                      \
        _Pragma("unroll")                                                     \
        for (int e = 0; e < 4; ++e) {                                         \
            const int row = (e << 7) + tid;                                   \
            xv[e][0] = s4[(row << 1) + (0 ^ swz)];                            \
            xv[e][1] = s4[(row << 1) + (1 ^ swz)];                            \
        }                                                                     \
        _Pragma("unroll")                                                     \
        for (int g = 0; g < 2; ++g) {                                         \
            _Pragma("unroll")                                                 \
            for (int q = 0; q < 4; ++q) {                                     \
                const int k = (C) * 8 + g * 4 + q;                            \
                const longlong2* Ap =                                         \
                    reinterpret_cast<const longlong2*>(sx + k * 20);          \
                long long a[10];                                              \
                _Pragma("unroll")                                             \
                for (int j = 0; j < 5; ++j) {                                 \
                    const longlong2 vv = Ap[j];                               \
                    a[2 * j] = vv.x;                                          \
                    a[2 * j + 1] = vv.y;                                      \
                }                                                             \
                _Pragma("unroll")                                             \
                for (int e = 0; e < 4; ++e) {                                 \
                    const float xk =                                          \
                        reinterpret_cast<const float*>(&xv[e][g])[q];         \
                    long long xx;                                             \
                    PACK_DUP(xx, xk);                                         \
                    _Pragma("unroll")                                         \
                    for (int p = 0; p < 10; ++p) FMA2(acc[e][p], a[p], xx);   \
                }                                                             \
            }                                                                 \
        }                                                                     \
    } while (0)

__global__ __launch_bounds__(128, 3) void cvqnn_main(
    const float* __restrict__ x, float* __restrict__ out, int B,
    const float* __restrict__ i1_0, const float* __restrict__ sq0,
    const float* __restrict__ i2_0, const float* __restrict__ d0,
    const float* __restrict__ i1_1, const float* __restrict__ sq1,
    const float* __restrict__ i2_1, const float* __restrict__ d1) {
    extern __shared__ float sx[];  // [A 1312f][b0 4096f][b1][b2][b3]
    const int tid = threadIdx.x;
    const int lane = tid & 31;
    const int wid = tid >> 5;
    const int base = blockIdx.x << 9;  // * 512 rows
    const int Bm1 = B - 1;
    const int swz = (tid >> 2) & 1;    // = (row>>2)&1 (e*128, wid*32 even)

    const float4* __restrict__ x4 = reinterpret_cast<const float4*>(x);
    unsigned sbase;
    asm("{ .reg .u64 t; cvta.to.shared.u64 t, %1; cvt.u32.u64 %0, t; }"
        : "=r"(sbase) : "l"(sx));

    if (blockIdx.x == 0) {
        run_setup(sx, i1_0, sq0, i2_0, d0, i1_1, sq1, i2_1, d1, tid);
    } else {
        if (tid == 0)
            while (g_flag == 0) __nanosleep(64);
        __syncthreads();
        __threadfence();
    }
    __syncthreads();  // setup scratch in sx is done

    // group 0: A -> shared (320 float4, block-cooperative)
    {
        const float4* gA4 = reinterpret_cast<const float4*>(g_A);
#pragma unroll
        for (int it = 0; it < 3; ++it) {
            const int i = it * 128 + tid;
            if (i < 320) {
                const unsigned sa = sbase + (unsigned)i * 16u;
                asm volatile("cp.async.cg.shared.global [%0], [%1], 16;"
                             :: "r"(sa), "l"(gA4 + i) : "memory");
            }
        }
        CP_COMMIT();
    }

    // groups 1..4: chunks 0..3 up-front, no wait yet
    STAGEW(0, 0);
    STAGEW(1, 1);
    STAGEW(2, 2);
    STAGEW(3, 3);

    // accumulators start at bias
    long long acc[4][10];
    {
        const long long* bp = reinterpret_cast<const long long*>(g_bias);
#pragma unroll
        for (int p = 0; p < 10; ++p) {
            const long long b = __ldg(bp + p);
#pragma unroll
            for (int e = 0; e < 4; ++e) acc[e][p] = b;
        }
    }

    CP_WAIT(4);        // A (oldest group) complete for every thread
    __syncthreads();   // A visible block-wide: the ONLY hot-path barrier

    // ring: wait chunk c, compute c, stage c+4 into the freed buffer
    // (buffer reuse is thread-local: LDS results of COMPUTE(c) are consumed
    //  by FFMA2s issued before the stage cp.asyncs in program order)
    CP_WAIT(3); __syncwarp(); COMPUTE(0, 0); STAGEW(4, 0);
    CP_WAIT(3); __syncwarp(); COMPUTE(1, 1); STAGEW(5, 1);
    CP_WAIT(3); __syncwarp(); COMPUTE(2, 2); STAGEW(6, 2);
    CP_WAIT(3); __syncwarp(); COMPUTE(3, 3); STAGEW(7, 3);
    CP_WAIT(3); __syncwarp(); COMPUTE(4, 0);
    CP_WAIT(2); __syncwarp(); COMPUTE(5, 1);
    CP_WAIT(1); __syncwarp(); COMPUTE(6, 2);
    CP_WAIT(0); __syncwarp(); COMPUTE(7, 3);

    // epilogue (no barriers; stores overlap other warps/blocks)
    long long c0p[5];
    {
        const long long* cp0 = reinterpret_cast<const long long*>(g_c0);
#pragma unroll
        for (int p = 0; p < 5; ++p) c0p[p] = __ldg(cp0 + p);
    }
#pragma unroll
    for (int e = 0; e < 4; ++e) {
        const int row = base + (e << 7) + tid;
        if (row < B) {
            float v[10];
#pragma unroll
            for (int p = 0; p < 5; ++p) {
                long long t1, t2, s;
                MUL2(t1, acc[e][p], acc[e][p]);
                MUL2(t2, acc[e][5 + p], acc[e][5 + p]);
                ADD2(s, t1, t2);
                ADD2(s, s, c0p[p]);
                float s0, s1;
                UNPACK2(s0, s1, s);
#pragma unroll
                for (int h = 0; h < 2; ++h) {
                    float nm = fmaxf((h == 0) ? s0 : s1, 0.0f);
                    const float big = __logf(1.0f + nm);
                    const float small =
                        nm * fmaf(nm, fmaf(nm, 0.33333333f, -0.5f), 1.0f);
                    v[2 * p + h] = (nm < 0.03125f) ? small : big;
                }
            }
            float2* op = reinterpret_cast<float2*>(out + (size_t)row * 10);
#pragma unroll
            for (int j = 0; j < 5; ++j)
                op[j] = make_float2(v[2 * j], v[2 * j + 1]);
        }
    }
}

extern "C" void kernel_launch(void* const* d_in, const int* in_sizes, int n_in,
                              void* d_out, int out_size) {
    const float* x = (const float*)d_in[0];
    const int B = in_sizes[0] / 64;
    const int ntiles = (B + 511) >> 9;

    cudaFuncSetAttribute(cvqnn_main,
                         cudaFuncAttributeMaxDynamicSharedMemorySize,
                         SMEM_BYTES);

    cvqnn_main<<<ntiles, 128, SMEM_BYTES>>>(
        x, (float*)d_out, B,
        (const float*)d_in[1], (const float*)d_in[2],
        (const float*)d_in[3], (const float*)d_in[4],
        (const float*)d_in[5], (const float*)d_in[6],
        (const float*)d_in[7], (const float*)d_in[8]);
}

// round 14
// speedup vs baseline: 1.3043x; 1.3043x over previous
#include <cuda_runtime.h>
#include <cstdint>

// ---------------------------------------------------------------------------
// CVQNN classifier: out[b,w] = log1p(relu(c0[w] + mx'^2 + mp'^2))
//   mx'[w] = sum_k A[k][w]   *x[b,k] + bias[w]     (A = S[rows,:64], bias=d/2)
//   mp'[w] = sum_k A[k][10+w]*x[b,k] + bias[10+w]
// Single launch, non-persistent grid, one 256-row tile per block. Block 0
// computes A/bias/c0 in-kernel, publishes via flag. 128 threads, 2 rows/thr.
// Pipeline: 3 smem quarter-buffers (occ 4, 16 warps/SM). Quarters q0..q2
// staged up-front; q3 reuses buffer 0, staged after COMPUTE(0) — warp-private
// slabs make the WAR thread-local and program-ordered. Zero block barriers
// in the hot path. (R12 structure, verified best; epilogue constants hoisted.)
// ---------------------------------------------------------------------------

__device__ __align__(16) float g_A[64 * 20];   // A[k][o] = S[rows[o], k]
__device__ __align__(16) float g_bias[20];     // d[rows[o]] / 2
__device__ __align__(16) float g_c0[10];       // cov_term[w]/4 - 0.5
__device__ volatile int g_flag = 0;            // 0 until first publish

// ---------------- f32x2 packed-math helpers --------------------------------
#define FMA2(acc, a, b) \
    asm("fma.rn.f32x2 %0, %1, %2, %0;" : "+l"(acc) : "l"(a), "l"(b))
#define MUL2(d, a, b) \
    asm("mul.rn.f32x2 %0, %1, %2;" : "=l"(d) : "l"(a), "l"(b))
#define ADD2(d, a, b) \
    asm("add.rn.f32x2 %0, %1, %2;" : "=l"(d) : "l"(a), "l"(b))
#define PACK_DUP(d, f) \
    asm("mov.b64 %0, {%1, %1};" : "=l"(d) : "f"(f))
#define UNPACK2(lo, hi, v) \
    asm("mov.b64 {%0, %1}, %2;" : "=f"(lo), "=f"(hi) : "l"(v))

// ---------------------------------------------------------------------------
// Setup (block 0 only, 128 threads): row-backward propagation v^T <- v^T * F.
// ---------------------------------------------------------------------------

__device__ __forceinline__ void bs_back(float v[20], float* sv,
                                        const float* p, int start, int tid) {
    const int m = tid & 63;
    const bool lower = tid < 64;
    const bool active = (m >= start) && (m < start + ((start == 0) ? 64 : 62));
#pragma unroll
    for (int w = 0; w < 20; ++w) sv[w * 132 + tid] = v[w];
    __syncthreads();
    if (active) {
        const int rel = m - start;
        const int i = start + (rel & ~1);
        const bool is_i = (rel & 1) == 0;
        float st_, ct_, sp_, cp_;
        __sincosf(p[3 * i], &st_, &ct_);
        __sincosf(p[3 * i + 1], &sp_, &cp_);
        const int o = is_i ? (i + 1) : i;
        const int sameIdx = (lower ? 0 : 64) + o;
        const int crossIdx = (lower ? 64 : 0) + o;
        const float cA1 = (is_i ? cp_ : -cp_) * st_;
        const float cA2 = (lower ? sp_ : -sp_) * st_;
#pragma unroll
        for (int w = 0; w < 20; ++w)
            v[w] = ct_ * v[w] + cA1 * sv[w * 132 + sameIdx]
                              + cA2 * sv[w * 132 + crossIdx];
    }
    __syncthreads();
}

__device__ __forceinline__ void r_back(float v[20], float* sv,
                                       const float* p, int tid) {
    const int k = tid & 63;
    const bool lower = tid < 64;
    float c_ = 1.0f, s_ = 0.0f;
    if (k < 63) __sincosf(p[3 * k + 2], &s_, &c_);
#pragma unroll
    for (int w = 0; w < 20; ++w) sv[w * 132 + tid] = v[w];
    __syncthreads();
    const float cs = lower ? s_ : -s_;
    const int cross = tid ^ 64;
#pragma unroll
    for (int w = 0; w < 20; ++w)
        v[w] = c_ * v[w] + cs * sv[w * 132 + cross];
    __syncthreads();
}

__device__ void run_setup(float* sv,
                          const float* i1_0, const float* sq0,
                          const float* i2_0, const float* d0,
                          const float* i1_1, const float* sq1,
                          const float* i2_1, const float* d1, int tid) {
    const int k = tid & 63;
    const bool lower = tid < 64;
    float v[20];
#pragma unroll
    for (int w = 0; w < 20; ++w) {
        const int r = (w < 10) ? w : (54 + w);  // rows = [0..9, 64..73]
        v[w] = (tid == r) ? 1.0f : 0.0f;
    }
    // ---- layer 1 (leftmost in S) ----
    bs_back(v, sv, i2_1, 1, tid);
    bs_back(v, sv, i2_1, 0, tid);
    {
        const float e = lower ? __expf(-sq1[k]) : __expf(sq1[k]);
#pragma unroll
        for (int w = 0; w < 20; ++w) v[w] *= e;
    }
    r_back(v, sv, i1_1, tid);
    bs_back(v, sv, i1_1, 1, tid);
    bs_back(v, sv, i1_1, 0, tid);
    // dot0 = row_r(M_L1) . [2*disp0; 0]
#pragma unroll
    for (int w = 0; w < 20; ++w)
        sv[w * 132 + tid] = lower ? v[w] * 2.0f * d0[tid] : 0.0f;
    __syncthreads();
    if (tid < 20) {
        float s = 0.0f;
        for (int t = 0; t < 64; ++t) s += sv[tid * 132 + t];
        sv[2640 + tid] = s;
    }
    __syncthreads();
    // ---- layer 0 ----
    bs_back(v, sv, i2_0, 1, tid);
    bs_back(v, sv, i2_0, 0, tid);
    {
        const float e = lower ? __expf(-sq0[k]) : __expf(sq0[k]);
#pragma unroll
        for (int w = 0; w < 20; ++w) v[w] *= e;
    }
    r_back(v, sv, i1_0, tid);
    bs_back(v, sv, i1_0, 1, tid);
    bs_back(v, sv, i1_0, 0, tid);
    // ---- outputs ----
    if (lower) {
#pragma unroll
        for (int o = 0; o < 20; ++o) g_A[tid * 20 + o] = v[o];
    }
#pragma unroll
    for (int w = 0; w < 10; ++w)
        sv[w * 132 + tid] = v[w] * v[w] + v[w + 10] * v[w + 10];
    __syncthreads();
    if (tid < 10) {
        float s = 0.0f;
        for (int t = 0; t < 128; ++t) s += sv[tid * 132 + t];
        g_c0[tid] = 0.25f * s - 0.5f;
    }
    if (tid < 20) {
        float b = 0.5f * sv[2640 + tid];
        if (tid < 10) b += d1[tid];
        g_bias[tid] = b;
    }
    __syncthreads();
    __threadfence();
    if (tid == 0) g_flag = 1;
}

// ---------------------------------------------------------------------------
// Main: 128 threads, 2 rows/thread, 256-row tile, 3 quarter buffers (occ 4).
// smem: A (1312 floats) + 3 buffers of 256 rows x 4 float4 (16 KB each).
// Swizzle: f4i = (row<<2) + (q ^ ((row>>1)&3))  -> conflict-free LDS.128.
// Warp w stages+computes rows {e*128 + w*32 + lane}: per-warp sync only.
// ---------------------------------------------------------------------------

#define A_FLOATS   1312
#define QBUF       4096                     // floats per quarter buffer
#define SMEM_BYTES ((A_FLOATS + 3 * QBUF) * 4)

#define CP_COMMIT() asm volatile("cp.async.commit_group;" ::: "memory")
#define CP_WAIT(N)  asm volatile("cp.async.wait_group %0;" :: "n"(N) : "memory")

// stage this warp's 64 rows of k-quarter QH into buffer BUF (8 x 16B/thread)
#define STAGEW(QH, BUF)                                                       \
    do {                                                                      \
        _Pragma("unroll")                                                     \
        for (int it = 0; it < 8; ++it) {                                      \
            const int flat = (it << 5) + lane;   /* 0..255 */                 \
            const int sr = flat >> 2, q = flat & 3;                           \
            const int rloc = (wid << 5) + sr + ((sr >> 5) * 96);              \
            int grow = base + rloc;                                           \
            if (grow > Bm1) grow = Bm1;                                       \
            const int f4i = (rloc << 2) + (q ^ ((rloc >> 1) & 3));            \
            const unsigned sa = sbase + (A_FLOATS * 4u) +                     \
                                (BUF) * (QBUF * 4u) + (unsigned)f4i * 16u;    \
            const float4* gp = x4 + (size_t)grow * 16 + (QH) * 4 + q;         \
            asm volatile("cp.async.cg.shared.global [%0], [%1], 16;"          \
                         :: "r"(sa), "l"(gp) : "memory");                     \
        }                                                                     \
        CP_COMMIT();                                                          \
    } while (0)

// consume k-quarter QH from buffer BUF: 16 k x 2 rows x 10 FFMA2
#define COMPUTE(QH, BUF)                                                      \
    do {                                                                      \
        const float4* s4 =                                                    \
            reinterpret_cast<const float4*>(sx + A_FLOATS + (BUF) * QBUF);    \
        _Pragma("unroll")                                                     \
        for (int kk = 0; kk < 4; ++kk) {                                      \
            float4 xv[2];                                                     \
            _Pragma("unroll")                                                 \
            for (int e = 0; e < 2; ++e)                                       \
                xv[e] = s4[(((e << 7) + tid) << 2) + (kk ^ sw)];              \
            _Pragma("unroll")                                                 \
            for (int q = 0; q < 4; ++q) {                                     \
                const int k = (QH) * 16 + kk * 4 + q;                         \
                const longlong2* Ap =                                         \
                    reinterpret_cast<const longlong2*>(sx + k * 20);          \
                long long a[10];                                              \
                _Pragma("unroll")                                             \
                for (int j = 0; j < 5; ++j) {                                 \
                    const longlong2 vv = Ap[j];                               \
                    a[2 * j] = vv.x;                                          \
                    a[2 * j + 1] = vv.y;                                      \
                }                                                             \
                _Pragma("unroll")                                             \
                for (int e = 0; e < 2; ++e) {                                 \
                    const float xk = reinterpret_cast<const float*>(&xv[e])[q]; \
                    long long xx;                                             \
                    PACK_DUP(xx, xk);                                         \
                    _Pragma("unroll")                                         \
                    for (int p = 0; p < 10; ++p) FMA2(acc[e][p], a[p], xx);   \
                }                                                             \
            }                                                                 \
        }                                                                     \
    } while (0)

__global__ __launch_bounds__(128, 4) void cvqnn_main(
    const float* __restrict__ x, float* __restrict__ out, int B,
    const float* __restrict__ i1_0, const float* __restrict__ sq0,
    const float* __restrict__ i2_0, const float* __restrict__ d0,
    const float* __restrict__ i1_1, const float* __restrict__ sq1,
    const float* __restrict__ i2_1, const float* __restrict__ d1) {
    extern __shared__ float sx[];  // [A 1312f][b0 4096f][b1][b2]
    const int tid = threadIdx.x;
    const int lane = tid & 31;
    const int wid = tid >> 5;
    const int base = blockIdx.x << 8;  // * 256 rows
    const int Bm1 = B - 1;
    const int sw = (tid >> 1) & 3;     // = (row>>1)&3 (e*128 contributes 0)

    const float4* __restrict__ x4 = reinterpret_cast<const float4*>(x);
    unsigned sbase;
    asm("{ .reg .u64 t; cvta.to.shared.u64 t, %1; cvt.u32.u64 %0, t; }"
        : "=r"(sbase) : "l"(sx));

    if (blockIdx.x == 0) {
        run_setup(sx, i1_0, sq0, i2_0, d0, i1_1, sq1, i2_1, d1, tid);
    } else {
        if (tid == 0)
            while (g_flag == 0) __nanosleep(64);
        __syncthreads();
    }
    __syncthreads();  // setup scratch in sx is done

    // group 0: A -> shared (320 float4, block-cooperative)
    {
        const float4* gA4 = reinterpret_cast<const float4*>(g_A);
#pragma unroll
        for (int it = 0; it < 3; ++it) {
            const int i = it * 128 + tid;
            if (i < 320) {
                const unsigned sa = sbase + (unsigned)i * 16u;
                asm volatile("cp.async.cg.shared.global [%0], [%1], 16;"
                             :: "r"(sa), "l"(gA4 + i) : "memory");
            }
        }
        CP_COMMIT();
    }

    // groups 1..3: this warp's quarters q0..q2, no wait yet
    STAGEW(0, 0);
    STAGEW(1, 1);
    STAGEW(2, 2);

    // accumulators start at bias; epilogue constants hoisted here so the
    // epilogue itself is pure register math (overlaps other warps' fetches)
    long long acc[2][10];
    long long c0p[5];
    {
        const long long* bp = reinterpret_cast<const long long*>(g_bias);
        const long long* cp0 = reinterpret_cast<const long long*>(g_c0);
#pragma unroll
        for (int p = 0; p < 10; ++p) {
            const long long b = __ldg(bp + p);
            acc[0][p] = b;
            acc[1][p] = b;
        }
#pragma unroll
        for (int p = 0; p < 5; ++p) c0p[p] = __ldg(cp0 + p);
    }

    CP_WAIT(3);        // A (oldest group) complete for every thread
    __syncthreads();   // A visible block-wide: the ONLY hot-path barrier

    CP_WAIT(2); __syncwarp(); COMPUTE(0, 0);  // warp-local q0 landed
    // Reuse buffer 0 for q3: all buffer-0 LDS results were consumed by
    // FFMA2s that issued before these cp.asyncs (program order) -> no WAR.
    STAGEW(3, 0);                             // group 4
    CP_WAIT(2); __syncwarp(); COMPUTE(1, 1);  // q1 landed (pending: q2,q3)
    CP_WAIT(1); __syncwarp(); COMPUTE(2, 2);  // q2 landed
    CP_WAIT(0); __syncwarp(); COMPUTE(3, 0);  // q3 landed

    // epilogue (no barriers, no loads; stores overlap other warps/blocks)
#pragma unroll
    for (int e = 0; e < 2; ++e) {
        const int row = base + (e << 7) + tid;
        if (row < B) {
            float v[10];
#pragma unroll
            for (int p = 0; p < 5; ++p) {
                long long t1, t2, s;
                MUL2(t1, acc[e][p], acc[e][p]);
                MUL2(t2, acc[e][5 + p], acc[e][5 + p]);
                ADD2(s, t1, t2);
                ADD2(s, s, c0p[p]);
                float s0, s1;
                UNPACK2(s0, s1, s);
#pragma unroll
                for (int h = 0; h < 2; ++h) {
                    float nm = fmaxf((h == 0) ? s0 : s1, 0.0f);
                    const float big = __logf(1.0f + nm);
                    const float small =
                        nm * fmaf(nm, fmaf(nm, 0.33333333f, -0.5f), 1.0f);
                    v[2 * p + h] = (nm < 0.03125f) ? small : big;
                }
            }
            float2* op = reinterpret_cast<float2*>(out + (size_t)row * 10);
#pragma unroll
            for (int j = 0; j < 5; ++j)
                op[j] = make_float2(v[2 * j], v[2 * j + 1]);
        }
    }
}

extern "C" void kernel_launch(void* const* d_in, const int* in_sizes, int n_in,
                              void* d_out, int out_size) {
    const float* x = (const float*)d_in[0];
    const int B = in_sizes[0] / 64;
    const int ntiles = (B + 255) >> 8;

    cudaFuncSetAttribute(cvqnn_main,
                         cudaFuncAttributeMaxDynamicSharedMemorySize,
                         SMEM_BYTES);

    cvqnn_main<<<ntiles, 128, SMEM_BYTES>>>(
        x, (float*)d_out, B,
        (const float*)d_in[1], (const float*)d_in[2],
        (const float*)d_in[3], (const float*)d_in[4],
        (const float*)d_in[5], (const float*)d_in[6],
        (const float*)d_in[7], (const float*)d_in[8]);
}